// round 11
// baseline (speedup 1.0000x reference)
#include <cuda_runtime.h>
#include <cuda_bf16.h>
#include <math.h>

#define VV 4
#define NN 1536
#define DD 256
#define E3 768
#define TOPK 32
#define M_TOTAL (VV*NN)   // 6144

#define BM 128
#define BN 64
#define BK 16

// ---------------- scratch (static __device__, no allocs) ----------------
__device__ float g_qkv[VV*NN*E3];        // (V,N,768) fp32
__device__ unsigned g_o32[VV*NN*DD];     // ircva output, tf32 bits
__device__ float g_aligned[VV*NN*DD];    // fp32 (k_final)
__device__ unsigned g_al32[VV*NN*DD];    // tf32 bits (k_qkvn A)
__device__ float g_Qn[VV*NN*DD];
__device__ __nv_bfloat16 g_Knb[VV*NN*DD];
__device__ __nv_bfloat16 g_Vnb[VV*NN*DD];
__device__ float g_Vmean[VV*DD];
__device__ float g_topm[VV*VV*NN*TOPK];  // raw top-k values (mask = >0)
__device__ int   g_topi[VV*VV*NN*TOPK];  // top-k column indices

// pre-converted tf32 operands
__device__ unsigned g_H32[VV*NN*DD];
__device__ unsigned g_inw32[E3*DD];
__device__ unsigned g_outw32[DD*DD];
__device__ unsigned g_wqkv32[3*VV*DD*DD]; // [which][v][DD][DD]

// ================= TF32 tensor-core GEMM (pre-converted operands) ========
__device__ __forceinline__ unsigned f2tf32(float x) {
    unsigned r;
    asm("cvt.rna.tf32.f32 %0, %1;" : "=r"(r) : "f"(x));
    return r;
}
__device__ __forceinline__ void mma_tf32(float c[4],
    unsigned a0, unsigned a1, unsigned a2, unsigned a3,
    unsigned b0, unsigned b1)
{
    asm volatile(
        "mma.sync.aligned.m16n8k8.row.col.f32.tf32.tf32.f32 "
        "{%0,%1,%2,%3},{%4,%5,%6,%7},{%8,%9},{%0,%1,%2,%3};"
        : "+f"(c[0]), "+f"(c[1]), "+f"(c[2]), "+f"(c[3])
        : "r"(a0), "r"(a1), "r"(a2), "r"(a3), "r"(b0), "r"(b1));
}

#define CPA16(dst, src) asm volatile("cp.async.cg.shared.global [%0], [%1], 16;\n" :: "r"(dst), "l"(src))
#define CP_COMMIT()     asm volatile("cp.async.commit_group;\n")
#define CP_WAIT1()      asm volatile("cp.async.wait_group 1;\n")

struct SmemGemm {
    unsigned A[2][BM][BK+4];   // +4 pad: conflict-free
    unsigned B[2][BN][BK+4];
};  // 30720 bytes

__device__ __forceinline__ void gemm_prefetch(SmemGemm* s, int buf,
    const unsigned* __restrict__ A, const unsigned* __restrict__ B,
    int Kd, int m0, int n0, int kt, int tid)
{
    #pragma unroll
    for (int i = 0; i < 2; i++) {
        int idx4 = tid + i * 256;
        int r = idx4 >> 2, c = (idx4 & 3) * 4;
        unsigned d = (unsigned)__cvta_generic_to_shared(&s->A[buf][r][c]);
        CPA16(d, A + (size_t)(m0 + r) * Kd + kt + c);
    }
    {
        int r = tid >> 2, c = (tid & 3) * 4;
        unsigned d = (unsigned)__cvta_generic_to_shared(&s->B[buf][r][c]);
        CPA16(d, B + (size_t)(n0 + r) * Kd + kt + c);
    }
}

__device__ __forceinline__ void gemm_compute(const SmemGemm* s, int buf,
                                             int warp, int lane, float acc[2][4][4])
{
    const int wm = warp >> 1, wn = warp & 1;
    #pragma unroll
    for (int ks = 0; ks < 2; ks++) {
        const int col = ks * 8 + (lane & 3);
        unsigned a[2][4], b[4][2];
        #pragma unroll
        for (int i = 0; i < 2; i++) {
            int row = wm * 32 + i * 16 + (lane >> 2);
            a[i][0] = s->A[buf][row  ][col  ];
            a[i][1] = s->A[buf][row+8][col  ];
            a[i][2] = s->A[buf][row  ][col+4];
            a[i][3] = s->A[buf][row+8][col+4];
        }
        #pragma unroll
        for (int j = 0; j < 4; j++) {
            int nr = wn * 32 + j * 8 + (lane >> 2);
            b[j][0] = s->B[buf][nr][col  ];
            b[j][1] = s->B[buf][nr][col+4];
        }
        #pragma unroll
        for (int i = 0; i < 2; i++)
            #pragma unroll
            for (int j = 0; j < 4; j++)
                mma_tf32(acc[i][j], a[i][0],a[i][1],a[i][2],a[i][3], b[j][0],b[j][1]);
    }
}

__device__ __forceinline__ void gemm_tf32(
    const unsigned* __restrict__ A, const unsigned* __restrict__ B, int Kd,
    int m0, int n0, SmemGemm* s, float acc[2][4][4])
{
    const int tid = threadIdx.x, lane = tid & 31, warp = tid >> 5;
    const int nk = Kd / BK;
    gemm_prefetch(s, 0, A, B, Kd, m0, n0, 0, tid);
    CP_COMMIT();
    for (int kt = 0; kt < nk; kt++) {
        if (kt + 1 < nk)
            gemm_prefetch(s, (kt + 1) & 1, A, B, Kd, m0, n0, (kt + 1) * BK, tid);
        CP_COMMIT();
        CP_WAIT1();
        __syncthreads();
        gemm_compute(s, kt & 1, warp, lane, acc);
        __syncthreads();
    }
}

// K0: convert fp32 inputs -> tf32 bit arrays (one float4 per thread)
#define H4  (VV*NN*DD/4)    // 393216
#define I4  (E3*DD/4)       // 49152
#define O4  (DD*DD/4)       // 16384
#define W4  (VV*DD*DD/4)    // 65536
#define CVT_TOTAL (H4 + I4 + O4 + 3*W4)   // 655360
__device__ __forceinline__ uint4 cvt4(const float4 v) {
    uint4 u;
    u.x = f2tf32(v.x); u.y = f2tf32(v.y); u.z = f2tf32(v.z); u.w = f2tf32(v.w);
    return u;
}
__global__ void k_cvt(const float* __restrict__ H, const float* __restrict__ inw,
                      const float* __restrict__ outw, const float* __restrict__ WQ,
                      const float* __restrict__ WK, const float* __restrict__ WV)
{
    int i = blockIdx.x * 256 + threadIdx.x;
    if (i >= CVT_TOTAL) return;
    if (i < H4) {
        ((uint4*)g_H32)[i] = cvt4(((const float4*)H)[i]); return;
    }
    i -= H4;
    if (i < I4) { ((uint4*)g_inw32)[i] = cvt4(((const float4*)inw)[i]); return; }
    i -= I4;
    if (i < O4) { ((uint4*)g_outw32)[i] = cvt4(((const float4*)outw)[i]); return; }
    i -= O4;
    if (i < W4) { ((uint4*)g_wqkv32)[i] = cvt4(((const float4*)WQ)[i]); return; }
    i -= W4;
    if (i < W4) { ((uint4*)(g_wqkv32 + VV*DD*DD))[i] = cvt4(((const float4*)WK)[i]); return; }
    i -= W4;
    ((uint4*)(g_wqkv32 + 2*VV*DD*DD))[i] = cvt4(((const float4*)WV)[i]);
}

// ---------------- top-k warp routine (barrier-free incremental argmax) ---
__device__ __forceinline__ void topk_warp(const float* __restrict__ C,
                                          float* s, int rid, int lane)
{
    const int pr = rid / NN;        // 0..11
    const int n  = rid - pr * NN;
    const int p  = pr / 3, qi = pr % 3;
    const int q  = qi + (qi >= p);

    const float4* row4 = (const float4*)(C + (((size_t)p * VV + q) * NN + n) * NN);
    #pragma unroll
    for (int j = 0; j < 12; j++) {
        int i4 = lane + 32 * j;
        ((float4*)s)[i4] = row4[i4];
    }
    __syncwarp();

    const float NEG = -3.4e38f;
    float lv = NEG; int li = lane * 48;
    #pragma unroll 4
    for (int t = 0; t < 48; t++) {
        float x = s[lane * 48 + t];
        if (x > lv) { lv = x; li = lane * 48 + t; }
    }

    float outv = 0.0f; int outi = 0;
    #pragma unroll 1
    for (int it = 0; it < TOPK; it++) {
        float bv = lv; int bi = li;
        #pragma unroll
        for (int off = 16; off; off >>= 1) {
            float ov = __shfl_xor_sync(0xffffffffu, bv, off);
            int   oi = __shfl_xor_sync(0xffffffffu, bi, off);
            if (ov > bv || (ov == bv && oi < bi)) { bv = ov; bi = oi; }
        }
        if (lane == it) { outv = bv; outi = bi; }

        int ow = bi / 48;
        if (lane == 0) s[bi] = NEG;
        __syncwarp();

        int base = ow * 48;
        float nv = s[base + lane]; int ni = base + lane;
        if (lane < 16) {
            float y = s[base + 32 + lane];
            if (y > nv) { nv = y; ni = base + 32 + lane; }
        }
        #pragma unroll
        for (int off = 16; off; off >>= 1) {
            float ov = __shfl_xor_sync(0xffffffffu, nv, off);
            int   oi = __shfl_xor_sync(0xffffffffu, ni, off);
            if (ov > nv || (ov == nv && oi < ni)) { nv = ov; ni = oi; }
        }
        if (lane == ow) { lv = nv; li = ni; }
    }

    size_t base = (((size_t)p * VV + q) * NN + n) * TOPK + lane;
    g_topm[base] = outv;
    g_topi[base] = outi;
}

// ============ K1 fused: qkv GEMM blocks + topk blocks in one launch =======
#define GEMM1_BLKS 576                    // (6144/128) * (768/64)
#define TOPK_WPB 8
#define TOPK_BLKS (12 * NN / TOPK_WPB)    // 2304

union SmemFused {
    SmemGemm g;
    float rows[TOPK_WPB][NN];             // 49152 bytes
};

__global__ void __launch_bounds__(256, 3) k_qkv_topk(
    const float* __restrict__ b, const float* __restrict__ C)
{
    __shared__ SmemFused sm;
    const int bx = blockIdx.x;
    const int lane = threadIdx.x & 31, warp = threadIdx.x >> 5;

    if (bx < GEMM1_BLKS) {
        float acc[2][4][4] = {};
        int m0 = (bx / 12) * BM, n0 = (bx % 12) * BN;
        gemm_tf32(g_H32, g_inw32, DD, m0, n0, &sm.g, acc);
        int wm = warp >> 1, wn = warp & 1;
        #pragma unroll
        for (int i = 0; i < 2; i++)
            #pragma unroll
            for (int j = 0; j < 4; j++) {
                int row = m0 + wm*32 + i*16 + (lane >> 2);
                int col = n0 + wn*32 + j*8 + (lane & 3)*2;
                g_qkv[(size_t)row*E3 + col  ]     = acc[i][j][0] + b[col];
                g_qkv[(size_t)row*E3 + col+1]     = acc[i][j][1] + b[col+1];
                g_qkv[(size_t)(row+8)*E3 + col  ] = acc[i][j][2] + b[col];
                g_qkv[(size_t)(row+8)*E3 + col+1] = acc[i][j][3] + b[col+1];
            }
    } else {
        int rid = (bx - GEMM1_BLKS) * TOPK_WPB + warp;
        topk_warp(C, &sm.rows[warp][0], rid, lane);
    }
}

// K2: tiny cross-view attention. One warp per (n, head). Writes tf32 bits.
__global__ void k_att()
{
    int w = blockIdx.x * 8 + (threadIdx.x >> 5);
    int lane = threadIdx.x & 31;
    int n = w >> 2, h = w & 3;

    float2 q[4], k[4], v[4];
    #pragma unroll
    for (int s = 0; s < 4; s++) {
        const float* base = g_qkv + ((size_t)s * NN + n) * E3 + h * 64 + 2 * lane;
        q[s] = *(const float2*)(base);
        k[s] = *(const float2*)(base + 256);
        v[s] = *(const float2*)(base + 512);
    }
    float att[4][4];
    #pragma unroll
    for (int s = 0; s < 4; s++)
        #pragma unroll
        for (int t = 0; t < 4; t++)
            att[s][t] = q[s].x * k[t].x + q[s].y * k[t].y;
    #pragma unroll
    for (int off = 16; off; off >>= 1)
        #pragma unroll
        for (int s = 0; s < 4; s++)
            #pragma unroll
            for (int t = 0; t < 4; t++)
                att[s][t] += __shfl_xor_sync(0xffffffffu, att[s][t], off);

    #pragma unroll
    for (int s = 0; s < 4; s++) {
        float a0 = att[s][0]*0.125f, a1 = att[s][1]*0.125f,
              a2 = att[s][2]*0.125f, a3 = att[s][3]*0.125f;
        float mx = fmaxf(fmaxf(a0,a1), fmaxf(a2,a3));
        float e0 = expf(a0-mx), e1 = expf(a1-mx), e2 = expf(a2-mx), e3 = expf(a3-mx);
        float inv = 1.0f / (e0+e1+e2+e3);
        float ox = (e0*v[0].x + e1*v[1].x + e2*v[2].x + e3*v[3].x) * inv;
        float oy = (e0*v[0].y + e1*v[1].y + e2*v[2].y + e3*v[3].y) * inv;
        uint2 u = make_uint2(f2tf32(ox), f2tf32(oy));
        *(uint2*)(g_o32 + ((size_t)s * NN + n) * DD + h * 64 + 2 * lane) = u;
    }
}

// K3: fusion = o @ out_proj_w^T + b; aligned = a*fusion + (1-a)*H
__global__ void __launch_bounds__(256, 3) k_outproj(
    const float* __restrict__ Hin, const float* __restrict__ b,
    const float* __restrict__ alphas)
{
    __shared__ SmemGemm s;
    float acc[2][4][4] = {};
    int m0 = blockIdx.y * BM, n0 = blockIdx.x * BN;
    gemm_tf32(g_o32, g_outw32, DD, m0, n0, &s, acc);
    int lane = threadIdx.x & 31, warp = threadIdx.x >> 5;
    int wm = warp >> 1, wn = warp & 1;
    #pragma unroll
    for (int i = 0; i < 2; i++)
        #pragma unroll
        for (int j = 0; j < 4; j++) {
            int row = m0 + wm*32 + i*16 + (lane >> 2);
            int col = n0 + wn*32 + j*8 + (lane & 3)*2;
            #pragma unroll
            for (int rr = 0; rr < 2; rr++) {
                int r = row + rr*8;
                float a = alphas[r / NN];
                size_t o0 = (size_t)r*DD + col;
                float v0 = a*(acc[i][j][rr*2  ] + b[col  ]) + (1.0f-a)*Hin[o0  ];
                float v1 = a*(acc[i][j][rr*2+1] + b[col+1]) + (1.0f-a)*Hin[o0+1];
                g_aligned[o0] = v0; g_aligned[o0+1] = v1;
                g_al32[o0] = f2tf32(v0); g_al32[o0+1] = f2tf32(v1);
            }
        }
}

// K4: Qn/Kn/Vn per-view GEMMs. Qn fp32; Kn/Vn bf16.
__global__ void __launch_bounds__(256, 3) k_qkvn()
{
    __shared__ SmemGemm s;
    float acc[2][4][4] = {};
    int z = blockIdx.z;
    int v = z / 3, which = z % 3;
    const unsigned* B = g_wqkv32 + ((size_t)which * VV + v) * DD * DD;
    const unsigned* A = g_al32 + (size_t)v * NN * DD;
    int m0 = blockIdx.y * BM, n0 = blockIdx.x * BN;
    gemm_tf32(A, B, DD, m0, n0, &s, acc);
    int lane = threadIdx.x & 31, warp = threadIdx.x >> 5;
    int wm = warp >> 1, wn = warp & 1;
    if (which == 0) {
        float* Out = g_Qn + (size_t)v * NN * DD;
        #pragma unroll
        for (int i = 0; i < 2; i++)
            #pragma unroll
            for (int j = 0; j < 4; j++) {
                int row = m0 + wm*32 + i*16 + (lane >> 2);
                int col = n0 + wn*32 + j*8 + (lane & 3)*2;
                Out[(size_t)row*DD + col  ]     = acc[i][j][0];
                Out[(size_t)row*DD + col+1]     = acc[i][j][1];
                Out[(size_t)(row+8)*DD + col  ] = acc[i][j][2];
                Out[(size_t)(row+8)*DD + col+1] = acc[i][j][3];
            }
    } else {
        __nv_bfloat16* Out = (which == 1 ? g_Knb : g_Vnb) + (size_t)v * NN * DD;
        #pragma unroll
        for (int i = 0; i < 2; i++)
            #pragma unroll
            for (int j = 0; j < 4; j++) {
                int row = m0 + wm*32 + i*16 + (lane >> 2);
                int col = n0 + wn*32 + j*8 + (lane & 3)*2;
                *(__nv_bfloat162*)&Out[(size_t)row*DD + col] =
                    __nv_bfloat162(__float2bfloat16_rn(acc[i][j][0]), __float2bfloat16_rn(acc[i][j][1]));
                *(__nv_bfloat162*)&Out[(size_t)(row+8)*DD + col] =
                    __nv_bfloat162(__float2bfloat16_rn(acc[i][j][2]), __float2bfloat16_rn(acc[i][j][3]));
            }
    }
}

// K5: Vmean[v,d] = mean_m Vn[v,m,d]  (from bf16 Vn)
__global__ void k_vmean()
{
    __shared__ float part[4][DD];
    int v = blockIdx.x;
    int d = threadIdx.x & 255;
    int g = threadIdx.x >> 8;
    float s = 0.0f;
    const __nv_bfloat16* base = g_Vnb + (size_t)v * NN * DD + d;
    for (int m = g * 384; m < (g + 1) * 384; m++)
        s += __bfloat162float(base[(size_t)m * DD]);
    part[g][d] = s;
    __syncthreads();
    if (g == 0)
        g_Vmean[v * DD + d] = (part[0][d] + part[1][d] + part[2][d] + part[3][d]) * (1.0f / NN);
}

// K7: sparse neighbor attention + final fusion. Lane-per-dot layout.
#define GN 2
__global__ void __launch_bounds__(256) k_final(
    const float* __restrict__ Hin, const float* __restrict__ aalign,
    const float* __restrict__ bbeta, float* __restrict__ out)
{
    __shared__ float sq[GN][DD];
    __shared__ float wts[GN][3][TOPK];
    __shared__ int   sidx[GN][3][TOPK];

    const int p  = blockIdx.y;
    const int n0 = blockIdx.x * GN;
    const int tid = threadIdx.x;
    const int warp = tid >> 5, lane = tid & 31;

    #pragma unroll
    for (int i = 0; i < GN; i++)
        sq[i][tid] = g_Qn[((size_t)p * NN + n0 + i) * DD + tid];
    __syncthreads();

    if (warp < GN * 3) {
        const int nl = warp / 3, qi = warp % 3;
        const int n = n0 + nl;
        const int q = qi + (qi >= p);
        size_t tb = (((size_t)p * VV + q) * NN + n) * TOPK + lane;
        int   m  = g_topi[tb];
        float mv = g_topm[tb];
        sidx[nl][qi][lane] = m;

        const uint4* kr = (const uint4*)(g_Knb + ((size_t)q * NN + m) * DD);
        const float* qp = &sq[nl][0];
        float a0 = 0.f, a1 = 0.f, a2 = 0.f, a3 = 0.f;
        #pragma unroll 8
        for (int c = 0; c < 32; c++) {
            uint4 kv = kr[c];
            float2 f0 = __bfloat1622float2(*(__nv_bfloat162*)&kv.x);
            float2 f1 = __bfloat1622float2(*(__nv_bfloat162*)&kv.y);
            float2 f2 = __bfloat1622float2(*(__nv_bfloat162*)&kv.z);
            float2 f3 = __bfloat1622float2(*(__nv_bfloat162*)&kv.w);
            const float* qc = qp + c * 8;
            a0 += qc[0]*f0.x + qc[1]*f0.y;
            a1 += qc[2]*f1.x + qc[3]*f1.y;
            a2 += qc[4]*f2.x + qc[5]*f2.y;
            a3 += qc[6]*f3.x + qc[7]*f3.y;
        }
        float x = (mv > 0.0f) ? ((a0 + a1) + (a2 + a3)) * 0.0625f : -1e9f;

        float mx = x;
        #pragma unroll
        for (int o = 16; o; o >>= 1) mx = fmaxf(mx, __shfl_xor_sync(0xffffffffu, mx, o));
        float e = expf(x - mx);
        float s = e;
        #pragma unroll
        for (int o = 16; o; o >>= 1) s += __shfl_xor_sync(0xffffffffu, s, o);
        wts[nl][qi][lane] = e / s;
    }
    __syncthreads();

    const int nl = tid >> 7;
    const int d  = (tid & 127) * 2;
    const int n  = n0 + nl;

    float accx = g_Vmean[p * DD + d];
    float accy = g_Vmean[p * DD + d + 1];
    #pragma unroll
    for (int qi = 0; qi < 3; qi++) {
        const int q = qi + (qi >= p);
        const __nv_bfloat16* vb = g_Vnb + (size_t)q * NN * DD + d;
        #pragma unroll 8
        for (int j = 0; j < TOPK; j++) {
            float w = wts[nl][qi][j];
            float2 vv = __bfloat1622float2(*(const __nv_bfloat162*)(vb + (size_t)sidx[nl][qi][j] * DD));
            accx += w * vv.x;
            accy += w * vv.y;
        }
    }

    size_t off = ((size_t)p * NN + n) * DD + d;
    float a = 1.0f / (1.0f + expf(-aalign[0]));
    float b = bbeta[0];
    float fx = fmaxf(a * g_aligned[off]   + (1.0f - a) * accx, 0.0f);
    float fy = fmaxf(a * g_aligned[off+1] + (1.0f - a) * accy, 0.0f);
    out[off]   = b * Hin[off]   + (1.0f - b) * fx;
    out[off+1] = b * Hin[off+1] + (1.0f - b) * fy;
}

extern "C" void kernel_launch(void* const* d_in, const int* in_sizes, int n_in,
                              void* d_out, int out_size)
{
    const float* H        = (const float*)d_in[0];
    const float* C        = (const float*)d_in[1];
    const float* WQ       = (const float*)d_in[2];
    const float* WK       = (const float*)d_in[3];
    const float* WV       = (const float*)d_in[4];
    const float* in_w     = (const float*)d_in[5];
    const float* in_b     = (const float*)d_in[6];
    const float* out_w    = (const float*)d_in[7];
    const float* out_b    = (const float*)d_in[8];
    const float* alphas   = (const float*)d_in[9];
    const float* aalign   = (const float*)d_in[10];
    const float* bbeta    = (const float*)d_in[11];
    float* out = (float*)d_out;

    k_cvt<<<(CVT_TOTAL + 255) / 256, 256>>>(H, in_w, out_w, WQ, WK, WV);
    // fused: qkv GEMM (blocks [0,576)) + topk (blocks [576,2880)) overlap on-chip
    k_qkv_topk<<<GEMM1_BLKS + TOPK_BLKS, 256>>>(in_b, C);
    k_att<<<768, 256>>>();
    k_outproj<<<dim3(DD / BN, M_TOTAL / BM), 256>>>(H, out_b, alphas);
    k_qkvn<<<dim3(DD / BN, NN / BM, 12), 256>>>();
    k_vmean<<<VV, 1024>>>();
    k_final<<<dim3(NN / GN, VV), 256>>>(H, aalign, bbeta, out);
}

// round 13
// speedup vs baseline: 1.0022x; 1.0022x over previous
#include <cuda_runtime.h>
#include <cuda_bf16.h>
#include <math.h>

#define VV 4
#define NN 1536
#define DD 256
#define E3 768
#define TOPK 32
#define M_TOTAL (VV*NN)   // 6144

#define BM 128
#define BN 64
#define BK 16

// ---------------- scratch (static __device__, no allocs) ----------------
__device__ float g_qkv[VV*NN*E3];        // (V,N,768) fp32
__device__ unsigned g_o32[VV*NN*DD];     // ircva output, tf32 bits
__device__ float g_aligned[VV*NN*DD];    // fp32 (k_final)
__device__ unsigned g_al32[VV*NN*DD];    // tf32 bits (k_qkvn A)
__device__ float g_Qn[VV*NN*DD];
__device__ __nv_bfloat16 g_Knb[VV*NN*DD];
__device__ __nv_bfloat16 g_Vnb[VV*NN*DD];
__device__ float g_Vmean[VV*DD];
__device__ float g_topm[VV*VV*NN*TOPK];  // raw top-k values (mask = >0)
__device__ int   g_topi[VV*VV*NN*TOPK];  // top-k column indices

// pre-converted tf32 operands
__device__ unsigned g_H32[VV*NN*DD];
__device__ unsigned g_inw32[E3*DD];
__device__ unsigned g_outw32[DD*DD];
__device__ unsigned g_wqkv32[3*VV*DD*DD]; // [which][v][DD][DD]

// ================= TF32 tensor-core GEMM (pre-converted operands) ========
__device__ __forceinline__ unsigned f2tf32(float x) {
    unsigned r;
    asm("cvt.rna.tf32.f32 %0, %1;" : "=r"(r) : "f"(x));
    return r;
}
__device__ __forceinline__ void mma_tf32(float c[4],
    unsigned a0, unsigned a1, unsigned a2, unsigned a3,
    unsigned b0, unsigned b1)
{
    asm volatile(
        "mma.sync.aligned.m16n8k8.row.col.f32.tf32.tf32.f32 "
        "{%0,%1,%2,%3},{%4,%5,%6,%7},{%8,%9},{%0,%1,%2,%3};"
        : "+f"(c[0]), "+f"(c[1]), "+f"(c[2]), "+f"(c[3])
        : "r"(a0), "r"(a1), "r"(a2), "r"(a3), "r"(b0), "r"(b1));
}

#define CPA16(dst, src) asm volatile("cp.async.cg.shared.global [%0], [%1], 16;\n" :: "r"(dst), "l"(src))
#define CP_COMMIT()     asm volatile("cp.async.commit_group;\n")
#define CP_WAIT1()      asm volatile("cp.async.wait_group 1;\n")

struct SmemGemm {
    unsigned A[2][BM][BK+4];   // +4 pad: conflict-free
    unsigned B[2][BN][BK+4];
};  // 30720 bytes

__device__ __forceinline__ void gemm_prefetch(SmemGemm* s, int buf,
    const unsigned* __restrict__ A, const unsigned* __restrict__ B,
    int Kd, int m0, int n0, int kt, int tid)
{
    #pragma unroll
    for (int i = 0; i < 2; i++) {
        int idx4 = tid + i * 256;
        int r = idx4 >> 2, c = (idx4 & 3) * 4;
        unsigned d = (unsigned)__cvta_generic_to_shared(&s->A[buf][r][c]);
        CPA16(d, A + (size_t)(m0 + r) * Kd + kt + c);
    }
    {
        int r = tid >> 2, c = (tid & 3) * 4;
        unsigned d = (unsigned)__cvta_generic_to_shared(&s->B[buf][r][c]);
        CPA16(d, B + (size_t)(n0 + r) * Kd + kt + c);
    }
}

__device__ __forceinline__ void gemm_compute(const SmemGemm* s, int buf,
                                             int warp, int lane, float acc[2][4][4])
{
    const int wm = warp >> 1, wn = warp & 1;
    #pragma unroll
    for (int ks = 0; ks < 2; ks++) {
        const int col = ks * 8 + (lane & 3);
        unsigned a[2][4], b[4][2];
        #pragma unroll
        for (int i = 0; i < 2; i++) {
            int row = wm * 32 + i * 16 + (lane >> 2);
            a[i][0] = s->A[buf][row  ][col  ];
            a[i][1] = s->A[buf][row+8][col  ];
            a[i][2] = s->A[buf][row  ][col+4];
            a[i][3] = s->A[buf][row+8][col+4];
        }
        #pragma unroll
        for (int j = 0; j < 4; j++) {
            int nr = wn * 32 + j * 8 + (lane >> 2);
            b[j][0] = s->B[buf][nr][col  ];
            b[j][1] = s->B[buf][nr][col+4];
        }
        #pragma unroll
        for (int i = 0; i < 2; i++)
            #pragma unroll
            for (int j = 0; j < 4; j++)
                mma_tf32(acc[i][j], a[i][0],a[i][1],a[i][2],a[i][3], b[j][0],b[j][1]);
    }
}

__device__ __forceinline__ void gemm_tf32(
    const unsigned* __restrict__ A, const unsigned* __restrict__ B, int Kd,
    int m0, int n0, SmemGemm* s, float acc[2][4][4])
{
    const int tid = threadIdx.x, lane = tid & 31, warp = tid >> 5;
    const int nk = Kd / BK;
    gemm_prefetch(s, 0, A, B, Kd, m0, n0, 0, tid);
    CP_COMMIT();
    for (int kt = 0; kt < nk; kt++) {
        if (kt + 1 < nk)
            gemm_prefetch(s, (kt + 1) & 1, A, B, Kd, m0, n0, (kt + 1) * BK, tid);
        CP_COMMIT();
        CP_WAIT1();
        __syncthreads();
        gemm_compute(s, kt & 1, warp, lane, acc);
        __syncthreads();
    }
}

// K0: convert fp32 inputs -> tf32 bit arrays (one float4 per thread)
#define H4  (VV*NN*DD/4)    // 393216
#define I4  (E3*DD/4)       // 49152
#define O4  (DD*DD/4)       // 16384
#define W4  (VV*DD*DD/4)    // 65536
#define CVT_TOTAL (H4 + I4 + O4 + 3*W4)   // 655360
__device__ __forceinline__ uint4 cvt4(const float4 v) {
    uint4 u;
    u.x = f2tf32(v.x); u.y = f2tf32(v.y); u.z = f2tf32(v.z); u.w = f2tf32(v.w);
    return u;
}
__global__ void k_cvt(const float* __restrict__ H, const float* __restrict__ inw,
                      const float* __restrict__ outw, const float* __restrict__ WQ,
                      const float* __restrict__ WK, const float* __restrict__ WV)
{
    int i = blockIdx.x * 256 + threadIdx.x;
    if (i >= CVT_TOTAL) return;
    if (i < H4) {
        ((uint4*)g_H32)[i] = cvt4(((const float4*)H)[i]); return;
    }
    i -= H4;
    if (i < I4) { ((uint4*)g_inw32)[i] = cvt4(((const float4*)inw)[i]); return; }
    i -= I4;
    if (i < O4) { ((uint4*)g_outw32)[i] = cvt4(((const float4*)outw)[i]); return; }
    i -= O4;
    if (i < W4) { ((uint4*)g_wqkv32)[i] = cvt4(((const float4*)WQ)[i]); return; }
    i -= W4;
    if (i < W4) { ((uint4*)(g_wqkv32 + VV*DD*DD))[i] = cvt4(((const float4*)WK)[i]); return; }
    i -= W4;
    ((uint4*)(g_wqkv32 + 2*VV*DD*DD))[i] = cvt4(((const float4*)WV)[i]);
}

// ---------------- top-k warp routine (barrier-free incremental argmax) ---
__device__ __forceinline__ void topk_warp(const float* __restrict__ C,
                                          float* s, int rid, int lane)
{
    const int pr = rid / NN;        // 0..11
    const int n  = rid - pr * NN;
    const int p  = pr / 3, qi = pr % 3;
    const int q  = qi + (qi >= p);

    const float4* row4 = (const float4*)(C + (((size_t)p * VV + q) * NN + n) * NN);
    #pragma unroll
    for (int j = 0; j < 12; j++) {
        int i4 = lane + 32 * j;
        ((float4*)s)[i4] = row4[i4];
    }
    __syncwarp();

    const float NEG = -3.4e38f;
    float lv = NEG; int li = lane * 48;
    #pragma unroll 4
    for (int t = 0; t < 48; t++) {
        float x = s[lane * 48 + t];
        if (x > lv) { lv = x; li = lane * 48 + t; }
    }

    float outv = 0.0f; int outi = 0;
    #pragma unroll 1
    for (int it = 0; it < TOPK; it++) {
        float bv = lv; int bi = li;
        #pragma unroll
        for (int off = 16; off; off >>= 1) {
            float ov = __shfl_xor_sync(0xffffffffu, bv, off);
            int   oi = __shfl_xor_sync(0xffffffffu, bi, off);
            if (ov > bv || (ov == bv && oi < bi)) { bv = ov; bi = oi; }
        }
        if (lane == it) { outv = bv; outi = bi; }

        int ow = bi / 48;
        if (lane == 0) s[bi] = NEG;
        __syncwarp();

        int base = ow * 48;
        float nv = s[base + lane]; int ni = base + lane;
        if (lane < 16) {
            float y = s[base + 32 + lane];
            if (y > nv) { nv = y; ni = base + 32 + lane; }
        }
        #pragma unroll
        for (int off = 16; off; off >>= 1) {
            float ov = __shfl_xor_sync(0xffffffffu, nv, off);
            int   oi = __shfl_xor_sync(0xffffffffu, ni, off);
            if (ov > nv || (ov == nv && oi < ni)) { nv = ov; ni = oi; }
        }
        if (lane == ow) { lv = nv; li = ni; }
    }

    size_t base = (((size_t)p * VV + q) * NN + n) * TOPK + lane;
    g_topm[base] = outv;
    g_topi[base] = outi;
}

// ============ K1 fused: qkv GEMM blocks + topk blocks in one launch =======
#define GEMM1_BLKS 576                    // (6144/128) * (768/64)
#define TOPK_WPB 8
#define TOPK_BLKS (12 * NN / TOPK_WPB)    // 2304

union SmemFused {
    SmemGemm g;
    float rows[TOPK_WPB][NN];             // 49152 bytes
};

__global__ void __launch_bounds__(256, 3) k_qkv_topk(
    const float* __restrict__ b, const float* __restrict__ C)
{
    __shared__ SmemFused sm;
    const int bx = blockIdx.x;
    const int lane = threadIdx.x & 31, warp = threadIdx.x >> 5;

    if (bx < GEMM1_BLKS) {
        float acc[2][4][4] = {};
        int m0 = (bx / 12) * BM, n0 = (bx % 12) * BN;
        gemm_tf32(g_H32, g_inw32, DD, m0, n0, &sm.g, acc);
        int wm = warp >> 1, wn = warp & 1;
        #pragma unroll
        for (int i = 0; i < 2; i++)
            #pragma unroll
            for (int j = 0; j < 4; j++) {
                int row = m0 + wm*32 + i*16 + (lane >> 2);
                int col = n0 + wn*32 + j*8 + (lane & 3)*2;
                g_qkv[(size_t)row*E3 + col  ]     = acc[i][j][0] + b[col];
                g_qkv[(size_t)row*E3 + col+1]     = acc[i][j][1] + b[col+1];
                g_qkv[(size_t)(row+8)*E3 + col  ] = acc[i][j][2] + b[col];
                g_qkv[(size_t)(row+8)*E3 + col+1] = acc[i][j][3] + b[col+1];
            }
    } else {
        int rid = (bx - GEMM1_BLKS) * TOPK_WPB + warp;
        topk_warp(C, &sm.rows[warp][0], rid, lane);
    }
}

// K2: tiny cross-view attention. One warp per (n, head). Writes tf32 bits.
__global__ void k_att()
{
    int w = blockIdx.x * 8 + (threadIdx.x >> 5);
    int lane = threadIdx.x & 31;
    int n = w >> 2, h = w & 3;

    float2 q[4], k[4], v[4];
    #pragma unroll
    for (int s = 0; s < 4; s++) {
        const float* base = g_qkv + ((size_t)s * NN + n) * E3 + h * 64 + 2 * lane;
        q[s] = *(const float2*)(base);
        k[s] = *(const float2*)(base + 256);
        v[s] = *(const float2*)(base + 512);
    }
    float att[4][4];
    #pragma unroll
    for (int s = 0; s < 4; s++)
        #pragma unroll
        for (int t = 0; t < 4; t++)
            att[s][t] = q[s].x * k[t].x + q[s].y * k[t].y;
    #pragma unroll
    for (int off = 16; off; off >>= 1)
        #pragma unroll
        for (int s = 0; s < 4; s++)
            #pragma unroll
            for (int t = 0; t < 4; t++)
                att[s][t] += __shfl_xor_sync(0xffffffffu, att[s][t], off);

    #pragma unroll
    for (int s = 0; s < 4; s++) {
        float a0 = att[s][0]*0.125f, a1 = att[s][1]*0.125f,
              a2 = att[s][2]*0.125f, a3 = att[s][3]*0.125f;
        float mx = fmaxf(fmaxf(a0,a1), fmaxf(a2,a3));
        float e0 = expf(a0-mx), e1 = expf(a1-mx), e2 = expf(a2-mx), e3 = expf(a3-mx);
        float inv = 1.0f / (e0+e1+e2+e3);
        float ox = (e0*v[0].x + e1*v[1].x + e2*v[2].x + e3*v[3].x) * inv;
        float oy = (e0*v[0].y + e1*v[1].y + e2*v[2].y + e3*v[3].y) * inv;
        uint2 u = make_uint2(f2tf32(ox), f2tf32(oy));
        *(uint2*)(g_o32 + ((size_t)s * NN + n) * DD + h * 64 + 2 * lane) = u;
    }
}

// K3: fusion = o @ out_proj_w^T + b; aligned = a*fusion + (1-a)*H
__global__ void __launch_bounds__(256, 3) k_outproj(
    const float* __restrict__ Hin, const float* __restrict__ b,
    const float* __restrict__ alphas)
{
    __shared__ SmemGemm s;
    float acc[2][4][4] = {};
    int m0 = blockIdx.y * BM, n0 = blockIdx.x * BN;
    gemm_tf32(g_o32, g_outw32, DD, m0, n0, &s, acc);
    int lane = threadIdx.x & 31, warp = threadIdx.x >> 5;
    int wm = warp >> 1, wn = warp & 1;
    #pragma unroll
    for (int i = 0; i < 2; i++)
        #pragma unroll
        for (int j = 0; j < 4; j++) {
            int row = m0 + wm*32 + i*16 + (lane >> 2);
            int col = n0 + wn*32 + j*8 + (lane & 3)*2;
            #pragma unroll
            for (int rr = 0; rr < 2; rr++) {
                int r = row + rr*8;
                float a = alphas[r / NN];
                size_t o0 = (size_t)r*DD + col;
                float v0 = a*(acc[i][j][rr*2  ] + b[col  ]) + (1.0f-a)*Hin[o0  ];
                float v1 = a*(acc[i][j][rr*2+1] + b[col+1]) + (1.0f-a)*Hin[o0+1];
                g_aligned[o0] = v0; g_aligned[o0+1] = v1;
                g_al32[o0] = f2tf32(v0); g_al32[o0+1] = f2tf32(v1);
            }
        }
}

// K4: Qn/Kn/Vn per-view GEMMs. Qn fp32; Kn/Vn bf16.
__global__ void __launch_bounds__(256, 3) k_qkvn()
{
    __shared__ SmemGemm s;
    float acc[2][4][4] = {};
    int z = blockIdx.z;
    int v = z / 3, which = z % 3;
    const unsigned* B = g_wqkv32 + ((size_t)which * VV + v) * DD * DD;
    const unsigned* A = g_al32 + (size_t)v * NN * DD;
    int m0 = blockIdx.y * BM, n0 = blockIdx.x * BN;
    gemm_tf32(A, B, DD, m0, n0, &s, acc);
    int lane = threadIdx.x & 31, warp = threadIdx.x >> 5;
    int wm = warp >> 1, wn = warp & 1;
    if (which == 0) {
        float* Out = g_Qn + (size_t)v * NN * DD;
        #pragma unroll
        for (int i = 0; i < 2; i++)
            #pragma unroll
            for (int j = 0; j < 4; j++) {
                int row = m0 + wm*32 + i*16 + (lane >> 2);
                int col = n0 + wn*32 + j*8 + (lane & 3)*2;
                Out[(size_t)row*DD + col  ]     = acc[i][j][0];
                Out[(size_t)row*DD + col+1]     = acc[i][j][1];
                Out[(size_t)(row+8)*DD + col  ] = acc[i][j][2];
                Out[(size_t)(row+8)*DD + col+1] = acc[i][j][3];
            }
    } else {
        __nv_bfloat16* Out = (which == 1 ? g_Knb : g_Vnb) + (size_t)v * NN * DD;
        #pragma unroll
        for (int i = 0; i < 2; i++)
            #pragma unroll
            for (int j = 0; j < 4; j++) {
                int row = m0 + wm*32 + i*16 + (lane >> 2);
                int col = n0 + wn*32 + j*8 + (lane & 3)*2;
                *(__nv_bfloat162*)&Out[(size_t)row*DD + col] =
                    __nv_bfloat162(__float2bfloat16_rn(acc[i][j][0]), __float2bfloat16_rn(acc[i][j][1]));
                *(__nv_bfloat162*)&Out[(size_t)(row+8)*DD + col] =
                    __nv_bfloat162(__float2bfloat16_rn(acc[i][j][2]), __float2bfloat16_rn(acc[i][j][3]));
            }
    }
}

// K5: Vmean[v,d] = mean_m Vn[v,m,d]  (from bf16 Vn)
__global__ void k_vmean()
{
    __shared__ float part[4][DD];
    int v = blockIdx.x;
    int d = threadIdx.x & 255;
    int g = threadIdx.x >> 8;
    float s = 0.0f;
    const __nv_bfloat16* base = g_Vnb + (size_t)v * NN * DD + d;
    for (int m = g * 384; m < (g + 1) * 384; m++)
        s += __bfloat162float(base[(size_t)m * DD]);
    part[g][d] = s;
    __syncthreads();
    if (g == 0)
        g_Vmean[v * DD + d] = (part[0][d] + part[1][d] + part[2][d] + part[3][d]) * (1.0f / NN);
}

// K7: sparse neighbor attention + final fusion. Lane-per-dot layout.
#define GN 2
__global__ void __launch_bounds__(256) k_final(
    const float* __restrict__ Hin, const float* __restrict__ aalign,
    const float* __restrict__ bbeta, float* __restrict__ out)
{
    __shared__ float sq[GN][DD];
    __shared__ float wts[GN][3][TOPK];
    __shared__ int   sidx[GN][3][TOPK];

    const int p  = blockIdx.y;
    const int n0 = blockIdx.x * GN;
    const int tid = threadIdx.x;
    const int warp = tid >> 5, lane = tid & 31;

    #pragma unroll
    for (int i = 0; i < GN; i++)
        sq[i][tid] = g_Qn[((size_t)p * NN + n0 + i) * DD + tid];
    __syncthreads();

    if (warp < GN * 3) {
        const int nl = warp / 3, qi = warp % 3;
        const int n = n0 + nl;
        const int q = qi + (qi >= p);
        size_t tb = (((size_t)p * VV + q) * NN + n) * TOPK + lane;
        int   m  = g_topi[tb];
        float mv = g_topm[tb];
        sidx[nl][qi][lane] = m;

        const uint4* kr = (const uint4*)(g_Knb + ((size_t)q * NN + m) * DD);
        const float* qp = &sq[nl][0];
        float a0 = 0.f, a1 = 0.f, a2 = 0.f, a3 = 0.f;
        #pragma unroll 8
        for (int c = 0; c < 32; c++) {
            uint4 kv = kr[c];
            float2 f0 = __bfloat1622float2(*(__nv_bfloat162*)&kv.x);
            float2 f1 = __bfloat1622float2(*(__nv_bfloat162*)&kv.y);
            float2 f2 = __bfloat1622float2(*(__nv_bfloat162*)&kv.z);
            float2 f3 = __bfloat1622float2(*(__nv_bfloat162*)&kv.w);
            const float* qc = qp + c * 8;
            a0 += qc[0]*f0.x + qc[1]*f0.y;
            a1 += qc[2]*f1.x + qc[3]*f1.y;
            a2 += qc[4]*f2.x + qc[5]*f2.y;
            a3 += qc[6]*f3.x + qc[7]*f3.y;
        }
        float x = (mv > 0.0f) ? ((a0 + a1) + (a2 + a3)) * 0.0625f : -1e9f;

        float mx = x;
        #pragma unroll
        for (int o = 16; o; o >>= 1) mx = fmaxf(mx, __shfl_xor_sync(0xffffffffu, mx, o));
        float e = expf(x - mx);
        float s = e;
        #pragma unroll
        for (int o = 16; o; o >>= 1) s += __shfl_xor_sync(0xffffffffu, s, o);
        wts[nl][qi][lane] = e / s;
    }
    __syncthreads();

    const int nl = tid >> 7;
    const int d  = (tid & 127) * 2;
    const int n  = n0 + nl;

    float accx = g_Vmean[p * DD + d];
    float accy = g_Vmean[p * DD + d + 1];
    #pragma unroll
    for (int qi = 0; qi < 3; qi++) {
        const int q = qi + (qi >= p);
        const __nv_bfloat16* vb = g_Vnb + (size_t)q * NN * DD + d;
        #pragma unroll 8
        for (int j = 0; j < TOPK; j++) {
            float w = wts[nl][qi][j];
            float2 vv = __bfloat1622float2(*(const __nv_bfloat162*)(vb + (size_t)sidx[nl][qi][j] * DD));
            accx += w * vv.x;
            accy += w * vv.y;
        }
    }

    size_t off = ((size_t)p * NN + n) * DD + d;
    float a = 1.0f / (1.0f + expf(-aalign[0]));
    float b = bbeta[0];
    float fx = fmaxf(a * g_aligned[off]   + (1.0f - a) * accx, 0.0f);
    float fy = fmaxf(a * g_aligned[off+1] + (1.0f - a) * accy, 0.0f);
    out[off]   = b * Hin[off]   + (1.0f - b) * fx;
    out[off+1] = b * Hin[off+1] + (1.0f - b) * fy;
}

extern "C" void kernel_launch(void* const* d_in, const int* in_sizes, int n_in,
                              void* d_out, int out_size)
{
    const float* H        = (const float*)d_in[0];
    const float* C        = (const float*)d_in[1];
    const float* WQ       = (const float*)d_in[2];
    const float* WK       = (const float*)d_in[3];
    const float* WV       = (const float*)d_in[4];
    const float* in_w     = (const float*)d_in[5];
    const float* in_b     = (const float*)d_in[6];
    const float* out_w    = (const float*)d_in[7];
    const float* out_b    = (const float*)d_in[8];
    const float* alphas   = (const float*)d_in[9];
    const float* aalign   = (const float*)d_in[10];
    const float* bbeta    = (const float*)d_in[11];
    float* out = (float*)d_out;

    k_cvt<<<(CVT_TOTAL + 255) / 256, 256>>>(H, in_w, out_w, WQ, WK, WV);
    // fused: qkv GEMM (blocks [0,576)) + topk (blocks [576,2880)) overlap on-chip
    k_qkv_topk<<<GEMM1_BLKS + TOPK_BLKS, 256>>>(in_b, C);
    k_att<<<768, 256>>>();
    k_outproj<<<dim3(DD / BN, M_TOTAL / BM), 256>>>(H, out_b, alphas);
    k_qkvn<<<dim3(DD / BN, NN / BM, 12), 256>>>();
    k_vmean<<<VV, 1024>>>();
    k_final<<<dim3(NN / GN, VV), 256>>>(H, aalign, bbeta, out);
}